// round 7
// baseline (speedup 1.0000x reference)
#include <cuda_runtime.h>

// Depthwise 3x3 conv with one-hot (hard-softmax) weight == pure spatial shift:
//   out[b,c,h,w] = x[b,c,h+dh,w+dw]  (zero outside), (dh,dw) = abs-argmax of
// the 9 weights (first max wins, matching jnp.argmax).
// Shapes fixed: B=16, C=64, H=256, W=256 fp32.
//
// R7 = R3's proven layout (32768 blocks, 256 thr, 2 warp-interleaved float4
// per thread, plain stores) with the dw=+-1 path rewritten as
//   1x aligned LDG.128 + 1x guarded LDG.32 (independent, no shuffle)
// instead of 4x LDG.32. Same dependence depth as R3, half the load issues.

#define H_DIM 256
#define W_DIM 256

__device__ __forceinline__ float4
load_shifted(const float* __restrict__ x, int v, int dh, int dw) {
    // v = float4 output index. W=256 -> 64 float4/row.
    const int w4 = v & 63;
    const int h  = (v >> 6) & 255;
    const int bc = v >> 14;

    float4 val = make_float4(0.f, 0.f, 0.f, 0.f);
    const int hi = h + dh;
    if ((unsigned)hi < (unsigned)H_DIM) {
        const float* __restrict__ row = x + ((long long)bc * H_DIM + hi) * W_DIM;
        const float4 f = __ldg(reinterpret_cast<const float4*>(row) + w4);
        if (dw == 0) {
            val = f;
        } else if (dw == 1) {
            // cols 4w4+1 .. 4w4+4 -> (f.y, f.z, f.w, row[4w4+4])
            const float s = (w4 == 63) ? 0.f : __ldg(row + (w4 << 2) + 4);
            val = make_float4(f.y, f.z, f.w, s);
        } else {  // dw == -1
            // cols 4w4-1 .. 4w4+2 -> (row[4w4-1], f.x, f.y, f.z)
            const float s = (w4 == 0) ? 0.f : __ldg(row + (w4 << 2) - 1);
            val = make_float4(s, f.x, f.y, f.z);
        }
    }
    return val;
}

__global__ void __launch_bounds__(256)
shift_v128_kernel(const float* __restrict__ x, const float* __restrict__ wt,
                  float* __restrict__ out) {
    __shared__ int s_dh, s_dw;
    if (threadIdx.x == 0) {
        float best = -1.0f;
        int bi = 0;
#pragma unroll
        for (int i = 0; i < 9; ++i) {
            float a = fabsf(__ldg(wt + i));
            if (a > best) { best = a; bi = i; }  // strict > : first max wins
        }
        s_dh = bi / 3 - 1;
        s_dw = bi % 3 - 1;
    }
    __syncthreads();
    const int dh = s_dh;
    const int dw = s_dw;

    // Block covers 512 consecutive float4s; thread t handles t and t+256.
    const int base = blockIdx.x * 512;
    const int v0 = base + threadIdx.x;
    const int v1 = v0 + 256;

    // Two independent coalesced streams (front-batched -> MLP 2-4 loads).
    float4 a = load_shifted(x, v0, dh, dw);
    float4 b = load_shifted(x, v1, dh, dw);

    float4* __restrict__ o4 = reinterpret_cast<float4*>(out);
    o4[v0] = a;
    o4[v1] = b;
}

extern "C" void kernel_launch(void* const* d_in, const int* in_sizes, int n_in,
                              void* d_out, int out_size) {
    const float* x  = (const float*)d_in[0];
    const float* wt = (const float*)d_in[1];
    float* out = (float*)d_out;

    const int n4 = out_size >> 2;   // 16,777,216 float4
    const int blocks = n4 / 512;    // 32768 blocks, 256 threads, 2 f4/thread
    shift_v128_kernel<<<blocks, 256>>>(x, wt, out);
}

// round 8
// speedup vs baseline: 1.0709x; 1.0709x over previous
#include <cuda_runtime.h>

// Depthwise 3x3 conv with one-hot (hard-softmax) weight == pure spatial shift:
//   out[b,c,h,w] = x[b,c,h+dh,w+dw]  (zero outside), (dh,dw) = abs-argmax of
// the 9 weights (first max wins, matching jnp.argmax).
// Shapes fixed: B=16, C=64, H=256, W=256 fp32.
//
// Converged configuration (best of 7 measured variants, 76.4us kernel,
// 6.3 TB/s combined R+W ~ the B300 LTS/HBM streaming ceiling):
//  - single fused kernel, per-block argmax (9 L2-hit loads)
//  - 2 warp-interleaved float4 streams per thread (MLP=2; >2 measured neutral)
//  - dw=+-1 path: 4x LDG.32 at 16B lane stride (measured FASTER than
//    LDG.128+scalar and than shuffle assembly)
//  - plain stores (streaming hints measured neutral-to-negative)
//  - flat 32768-block grid (persistent grid measured negative)

#define H_DIM 256
#define W_DIM 256

__device__ __forceinline__ float4
load_shifted(const float* __restrict__ x, int v, int dh, int dw) {
    // v = float4 output index. W=256 -> 64 float4/row.
    const int w4 = v & 63;
    const int h  = (v >> 6) & 255;
    const int bc = v >> 14;

    float4 val = make_float4(0.f, 0.f, 0.f, 0.f);
    const int hi = h + dh;
    if ((unsigned)hi < (unsigned)H_DIM) {
        const float* __restrict__ row = x + ((long long)bc * H_DIM + hi) * W_DIM;
        if (dw == 0) {
            val = __ldg(reinterpret_cast<const float4*>(row) + w4);
        } else {
            // Lane addresses stride 16B across the warp -> well coalesced.
            const int wa = (w4 << 2) + dw;
            val.x = ((unsigned)wa       < (unsigned)W_DIM) ? __ldg(row + wa)     : 0.f;
            val.y = ((unsigned)(wa + 1) < (unsigned)W_DIM) ? __ldg(row + wa + 1) : 0.f;
            val.z = ((unsigned)(wa + 2) < (unsigned)W_DIM) ? __ldg(row + wa + 2) : 0.f;
            val.w = ((unsigned)(wa + 3) < (unsigned)W_DIM) ? __ldg(row + wa + 3) : 0.f;
        }
    }
    return val;
}

__global__ void __launch_bounds__(256)
shift_fused2_kernel(const float* __restrict__ x, const float* __restrict__ wt,
                    float* __restrict__ out) {
    __shared__ int s_dh, s_dw;
    if (threadIdx.x == 0) {
        float best = -1.0f;
        int bi = 0;
#pragma unroll
        for (int i = 0; i < 9; ++i) {
            float a = fabsf(__ldg(wt + i));
            if (a > best) { best = a; bi = i; }  // strict > : first max wins
        }
        s_dh = bi / 3 - 1;
        s_dw = bi % 3 - 1;
    }
    __syncthreads();
    const int dh = s_dh;
    const int dw = s_dw;

    // Block covers 512 consecutive float4s; thread t handles t and t+256.
    const int base = blockIdx.x * 512;
    const int v0 = base + threadIdx.x;
    const int v1 = v0 + 256;

    // Two independent load chains (front-batched by the compiler -> MLP 2).
    float4 a = load_shifted(x, v0, dh, dw);
    float4 b = load_shifted(x, v1, dh, dw);

    float4* __restrict__ o4 = reinterpret_cast<float4*>(out);
    o4[v0] = a;
    o4[v1] = b;
}

extern "C" void kernel_launch(void* const* d_in, const int* in_sizes, int n_in,
                              void* d_out, int out_size) {
    const float* x  = (const float*)d_in[0];
    const float* wt = (const float*)d_in[1];
    float* out = (float*)d_out;

    const int n4 = out_size >> 2;          // 16,777,216 float4
    const int blocks = n4 / 512;           // 32768 blocks, 256 threads, 2 f4/thread
    shift_fused2_kernel<<<blocks, 256>>>(x, wt, out);
}